// round 14
// baseline (speedup 1.0000x reference)
#include <cuda_runtime.h>

// Approx-MUFU helpers (relative err ~2e-7; measured harmless).
__device__ __forceinline__ float frcp_fast(float x) {
    float r; asm("rcp.approx.f32 %0, %1;" : "=f"(r) : "f"(x)); return r;
}
__device__ __forceinline__ float fsqrt_fast(float x) {
    float r; asm("sqrt.approx.f32 %0, %1;" : "=f"(r) : "f"(x)); return r;
}

// Custom sincos for moderate |x|. 3-step fused Cody-Waite reduction keeps the
// reduced argument accurate to ~1e-13 absolute, so cos(x)=±sin(r) near the
// zeros of cos retains ~ulp RELATIVE accuracy — the property the chaotic
// pitch path requires. Polys: cephes float minimax.
__device__ __forceinline__ void sincos_mid(float x, float* s, float* c) {
    const float T2OPI    = 0.63661977236758134308f;       // 2/pi
    const float PIO2_HI  = 1.57079601287841796875f;
    const float PIO2_MID = 3.1391647326015867e-07f;
    const float PIO2_LO  = 5.3903025299577648e-15f;

    float j = rintf(x * T2OPI);
    int   q = (int)j;
    float r = fmaf(j, -PIO2_HI, x);
    r = fmaf(j, -PIO2_MID, r);
    r = fmaf(j, -PIO2_LO, r);

    float r2 = r * r;
    float ps = fmaf(r2, fmaf(r2, -1.9515296e-4f, 8.3321608e-3f), -1.6666655e-1f);
    float s_r = fmaf(r * r2, ps, r);
    float pc = fmaf(r2, fmaf(r2, fmaf(r2, 2.4433157e-5f, -1.3887316e-3f), 4.1666646e-2f), -0.5f);
    float c_r = fmaf(r2, pc, 1.0f);

    bool swap = (q & 1);
    float ss = swap ? c_r : s_r;
    float cc = swap ? s_r : c_r;
    if (q & 2)       ss = -ss;
    if ((q + 1) & 2) cc = -cc;
    *s = ss; *c = cc;
}

// s = [vx,vy,vz, roll,pitch,yaw, wx,wy,wz]
__device__ __forceinline__ void dyn9(
    const float* __restrict__ s,
    float u0, float txI, float tyI, float tzI,
    float A0, float A1, float A2,
    float g0, float g1, float g2,
    float* __restrict__ d)
{
    float vx = s[0], vy = s[1], vz = s[2];
    float wx = s[6], wy = s[7], wz = s[8];

    float sr, cr, sp, cp, sy, cy;
    __sincosf(s[3], &sr, &cr);
    sincos_mid(s[4], &sp, &cp);
    __sincosf(s[5], &sy, &cy);

    // R[:, :, 2] thrust column
    float spcr = sp * cr;
    float r2x = fmaf(cy, spcr, sy * sr);
    float r2y = fmaf(sy, spcr, -(cy * sr));
    float r2z = cp * cr;

    // drag
    float n2 = fmaf(vx, vx, fmaf(vy, vy, vz * vz));
    float vn = fmaxf(fsqrt_fast(n2), 1e-8f);
    float nk = -0.05f * vn;

    d[0] = fmaf(r2x, u0, fmaf(nk, vx, g0));
    d[1] = fmaf(r2y, u0, fmaf(nk, vy, g1));
    d[2] = fmaf(r2z, u0, fmaf(nk, vz, g2));

    // omega_dot via folded gyro coefficients
    d[6] = fmaf(-A0, wy * wz, txI);
    d[7] = fmaf(-A1, wz * wx, tyI);
    d[8] = fmaf(-A2, wx * wy, tzI);

    // attitude kinematics
    float cpit = (fabsf(cp) < 1e-6f) ? 1e-6f : cp;
    float icp  = frcp_fast(cpit);
    float tp   = sp * icp;
    float q    = fmaf(sr, wy, cr * wz);
    d[3] = fmaf(tp, q, wx);
    d[4] = fmaf(cr, wy, -(sr * wz));
    d[5] = q * icp;
}

__global__ void __launch_bounds__(256, 5)
drone_rk4_kernel(const float4* __restrict__ st4,
                 const float4* __restrict__ u4,
                 const float*  __restrict__ Ip,
                 const float*  __restrict__ gp,
                 float4* __restrict__ out4,
                 int B)
{
    // Transpose-staging buffer: part-major layout sbuf[p*256 + row] so that
    //  - global phase: consecutive threads touch consecutive float4s (nL=4)
    //  - compute phase: thread t reads/writes [t], [256+t], [512+t] via
    //    conflict-free LDS.128/STS.128.
    __shared__ float4 sbuf[768];

    int tid  = threadIdx.x;
    int i    = blockIdx.x * 256 + tid;
    int base = blockIdx.x * 768;          // block's first float4 in st4/out4
    int limit = 3 * B;                    // total float4s

    // ---- coalesced load phase ----
    #pragma unroll
    for (int kk = 0; kk < 3; kk++) {
        int q  = tid + 256 * kk;
        int gq = base + q;
        if (gq < limit) {
            float4 v = __ldcs(&st4[gq]);
            sbuf[(q % 3) * 256 + (q / 3)] = v;
        }
    }
    __syncthreads();

    bool act = (i < B);
    int  iu  = act ? i : (B - 1);

    float4 a = sbuf[tid];          // p0 p1 p2 v0
    float4 b = sbuf[256 + tid];    // v1 v2 r  p
    float4 c = sbuf[512 + tid];    // y  w0 w1 w2
    float4 uu = __ldcs(&u4[iu]);   // u0 tau0 tau1 tau2

    float I0 = __ldg(Ip + 0), I1 = __ldg(Ip + 1), I2 = __ldg(Ip + 2);
    float g0 = __ldg(gp + 0), g1 = __ldg(gp + 1), g2 = __ldg(gp + 2);
    float iI0 = __frcp_rn(I0), iI1 = __frcp_rn(I1), iI2 = __frcp_rn(I2);
    float txI = uu.y * iI0, tyI = uu.z * iI1, tzI = uu.w * iI2;
    float A0 = (I2 - I1) * iI0;
    float A1 = (I0 - I2) * iI1;
    float A2 = (I1 - I0) * iI2;
    float u0 = uu.x;

    float y[9] = { a.w, b.x, b.y,   // vel
                   b.z, b.w, c.x,   // att
                   c.y, c.z, c.w }; // omega

    const float H2 = 0.005f;                  // 0.5*DT
    const float H1 = 0.01f;                   // DT
    const float W6 = (float)(0.01 / 6.0);     // DT/6

    float k[9], t[9], acc[9];

    // ---- k1 ----
    dyn9(y, u0, txI, tyI, tzI, A0, A1, A2, g0, g1, g2, k);
    #pragma unroll
    for (int j = 0; j < 9; j++) { acc[j] = k[j]; t[j] = fmaf(H2, k[j], y[j]); }
    float sax = k[0], say = k[1], saz = k[2];   // sum of stage accelerations 1..3

    // ---- k2 ----
    dyn9(t, u0, txI, tyI, tzI, A0, A1, A2, g0, g1, g2, k);
    #pragma unroll
    for (int j = 0; j < 9; j++) { acc[j] = fmaf(2.0f, k[j], acc[j]); t[j] = fmaf(H2, k[j], y[j]); }
    sax += k[0]; say += k[1]; saz += k[2];

    // ---- k3 ----
    dyn9(t, u0, txI, tyI, tzI, A0, A1, A2, g0, g1, g2, k);
    #pragma unroll
    for (int j = 0; j < 9; j++) { acc[j] = fmaf(2.0f, k[j], acc[j]); t[j] = fmaf(H1, k[j], y[j]); }
    sax += k[0]; say += k[1]; saz += k[2];

    // ---- k4 ----
    dyn9(t, u0, txI, tyI, tzI, A0, A1, A2, g0, g1, g2, k);
    #pragma unroll
    for (int j = 0; j < 9; j++) acc[j] += k[j];

    // position: p + DT*y_vel + (DT*DT/6)*sacc
    const float WP = (float)(0.01 * 0.01 / 6.0);
    float4 oa, ob, oc;
    oa.x = fmaf(WP, sax, fmaf(H1, y[0], a.x));
    oa.y = fmaf(WP, say, fmaf(H1, y[1], a.y));
    oa.z = fmaf(WP, saz, fmaf(H1, y[2], a.z));
    oa.w = fmaf(W6, acc[0], y[0]);
    ob.x = fmaf(W6, acc[1], y[1]);
    ob.y = fmaf(W6, acc[2], y[2]);
    ob.z = fmaf(W6, acc[3], y[3]);
    ob.w = fmaf(W6, acc[4], y[4]);
    oc.x = fmaf(W6, acc[5], y[5]);
    oc.y = fmaf(W6, acc[6], y[6]);
    oc.z = fmaf(W6, acc[7], y[7]);
    oc.w = fmaf(W6, acc[8], y[8]);

    // ---- coalesced store phase ----
    __syncthreads();   // all LDS of the load image complete before overwrite
    if (act) {
        sbuf[tid]       = oa;
        sbuf[256 + tid] = ob;
        sbuf[512 + tid] = oc;
    }
    __syncthreads();

    #pragma unroll
    for (int kk = 0; kk < 3; kk++) {
        int q  = tid + 256 * kk;
        int gq = base + q;
        if (gq < limit) {
            float4 v = sbuf[(q % 3) * 256 + (q / 3)];
            __stcs(&out4[gq], v);
        }
    }
}

extern "C" void kernel_launch(void* const* d_in, const int* in_sizes, int n_in,
                              void* d_out, int out_size)
{
    const float4* st = (const float4*)d_in[0];
    const float4* u  = (const float4*)d_in[1];
    const float*  I  = (const float*)d_in[2];
    const float*  g  = (const float*)d_in[3];
    float4* out = (float4*)d_out;

    int B = in_sizes[0] / 12;
    int threads = 256;
    int blocks = (B + threads - 1) / threads;
    drone_rk4_kernel<<<blocks, threads>>>(st, u, I, g, out, B);
}

// round 15
// speedup vs baseline: 1.0396x; 1.0396x over previous
#include <cuda_runtime.h>

// Approx-MUFU helpers (relative err ~2e-7; measured harmless).
__device__ __forceinline__ float frcp_fast(float x) {
    float r; asm("rcp.approx.f32 %0, %1;" : "=f"(r) : "f"(x)); return r;
}
__device__ __forceinline__ float fsqrt_fast(float x) {
    float r; asm("sqrt.approx.f32 %0, %1;" : "=f"(r) : "f"(x)); return r;
}

// Custom sincos for moderate |x|. 3-step fused Cody-Waite reduction keeps the
// reduced argument accurate to ~1e-13 absolute, so cos(x)=±sin(r) near the
// zeros of cos retains ~ulp RELATIVE accuracy — the property the chaotic
// pitch path requires. Polys: cephes float minimax.
__device__ __forceinline__ void sincos_mid(float x, float* s, float* c) {
    const float T2OPI    = 0.63661977236758134308f;       // 2/pi
    const float PIO2_HI  = 1.57079601287841796875f;
    const float PIO2_MID = 3.1391647326015867e-07f;
    const float PIO2_LO  = 5.3903025299577648e-15f;

    float j = rintf(x * T2OPI);
    int   q = (int)j;
    float r = fmaf(j, -PIO2_HI, x);
    r = fmaf(j, -PIO2_MID, r);
    r = fmaf(j, -PIO2_LO, r);

    float r2 = r * r;
    float ps = fmaf(r2, fmaf(r2, -1.9515296e-4f, 8.3321608e-3f), -1.6666655e-1f);
    float s_r = fmaf(r * r2, ps, r);
    float pc = fmaf(r2, fmaf(r2, fmaf(r2, 2.4433157e-5f, -1.3887316e-3f), 4.1666646e-2f), -0.5f);
    float c_r = fmaf(r2, pc, 1.0f);

    bool swap = (q & 1);
    float ss = swap ? c_r : s_r;
    float cc = swap ? s_r : c_r;
    if (q & 2)       ss = -ss;
    if ((q + 1) & 2) cc = -cc;
    *s = ss; *c = cc;
}

// s = [vx,vy,vz, roll,pitch,yaw, wx,wy,wz]
__device__ __forceinline__ void dyn9(
    const float* __restrict__ s,
    float u0, float txI, float tyI, float tzI,
    float A0, float A1, float A2,
    float g0, float g1, float g2,
    float* __restrict__ d)
{
    float vx = s[0], vy = s[1], vz = s[2];
    float wx = s[6], wy = s[7], wz = s[8];

    float sr, cr, sp, cp, sy, cy;
    __sincosf(s[3], &sr, &cr);
    sincos_mid(s[4], &sp, &cp);
    __sincosf(s[5], &sy, &cy);

    // R[:, :, 2] thrust column
    float spcr = sp * cr;
    float r2x = fmaf(cy, spcr, sy * sr);
    float r2y = fmaf(sy, spcr, -(cy * sr));
    float r2z = cp * cr;

    // drag
    float n2 = fmaf(vx, vx, fmaf(vy, vy, vz * vz));
    float vn = fmaxf(fsqrt_fast(n2), 1e-8f);
    float nk = -0.05f * vn;

    d[0] = fmaf(r2x, u0, fmaf(nk, vx, g0));
    d[1] = fmaf(r2y, u0, fmaf(nk, vy, g1));
    d[2] = fmaf(r2z, u0, fmaf(nk, vz, g2));

    // omega_dot via folded gyro coefficients
    d[6] = fmaf(-A0, wy * wz, txI);
    d[7] = fmaf(-A1, wz * wx, tyI);
    d[8] = fmaf(-A2, wx * wy, tzI);

    // attitude kinematics
    float cpit = (fabsf(cp) < 1e-6f) ? 1e-6f : cp;
    float icp  = frcp_fast(cpit);
    float tp   = sp * icp;
    float q    = fmaf(sr, wy, cr * wz);
    d[3] = fmaf(tp, q, wx);
    d[4] = fmaf(cr, wy, -(sr * wz));
    d[5] = q * icp;
}

// Partition stride in float4s. S%8==3 makes the bank-group map
// (3*(q%3) + q/3) mod 8 a complete residue system over any 8 consecutive q
// => conflict-free 128-bit smem access in BOTH phases.
#define SBUF_S 259

__global__ void __launch_bounds__(256, 5)
drone_rk4_kernel(const float4* __restrict__ st4,
                 const float4* __restrict__ u4,
                 const float*  __restrict__ Ip,
                 const float*  __restrict__ gp,
                 float4* __restrict__ out4,
                 int B)
{
    __shared__ float4 sbuf[3 * SBUF_S];

    int tid  = threadIdx.x;
    int i    = blockIdx.x * 256 + tid;
    int base = blockIdx.x * 768;          // block's first float4 in st4/out4
    int limit = 3 * B;                    // total float4s

    // ---- coalesced load phase (nL=4 per warp-LDG) ----
    #pragma unroll
    for (int kk = 0; kk < 3; kk++) {
        int q  = tid + 256 * kk;
        int gq = base + q;
        if (gq < limit) {
            float4 v = __ldcs(&st4[gq]);
            sbuf[(q % 3) * SBUF_S + (q / 3)] = v;
        }
    }
    __syncthreads();

    bool act = (i < B);
    int  iu  = act ? i : (B - 1);

    float4 a = sbuf[tid];                  // p0 p1 p2 v0
    float4 b = sbuf[SBUF_S + tid];         // v1 v2 r  p
    float4 c = sbuf[2 * SBUF_S + tid];     // y  w0 w1 w2
    float4 uu = __ldcs(&u4[iu]);           // u0 tau0 tau1 tau2

    float I0 = __ldg(Ip + 0), I1 = __ldg(Ip + 1), I2 = __ldg(Ip + 2);
    float g0 = __ldg(gp + 0), g1 = __ldg(gp + 1), g2 = __ldg(gp + 2);
    float iI0 = __frcp_rn(I0), iI1 = __frcp_rn(I1), iI2 = __frcp_rn(I2);
    float txI = uu.y * iI0, tyI = uu.z * iI1, tzI = uu.w * iI2;
    float A0 = (I2 - I1) * iI0;
    float A1 = (I0 - I2) * iI1;
    float A2 = (I1 - I0) * iI2;
    float u0 = uu.x;

    float y[9] = { a.w, b.x, b.y,   // vel
                   b.z, b.w, c.x,   // att
                   c.y, c.z, c.w }; // omega

    const float H2 = 0.005f;                  // 0.5*DT
    const float H1 = 0.01f;                   // DT
    const float W6 = (float)(0.01 / 6.0);     // DT/6

    float k[9], t[9], acc[9];

    // ---- k1 ----
    dyn9(y, u0, txI, tyI, tzI, A0, A1, A2, g0, g1, g2, k);
    #pragma unroll
    for (int j = 0; j < 9; j++) { acc[j] = k[j]; t[j] = fmaf(H2, k[j], y[j]); }
    float sax = k[0], say = k[1], saz = k[2];   // sum of stage accelerations 1..3

    // ---- k2 ----
    dyn9(t, u0, txI, tyI, tzI, A0, A1, A2, g0, g1, g2, k);
    #pragma unroll
    for (int j = 0; j < 9; j++) { acc[j] = fmaf(2.0f, k[j], acc[j]); t[j] = fmaf(H2, k[j], y[j]); }
    sax += k[0]; say += k[1]; saz += k[2];

    // ---- k3 ----
    dyn9(t, u0, txI, tyI, tzI, A0, A1, A2, g0, g1, g2, k);
    #pragma unroll
    for (int j = 0; j < 9; j++) { acc[j] = fmaf(2.0f, k[j], acc[j]); t[j] = fmaf(H1, k[j], y[j]); }
    sax += k[0]; say += k[1]; saz += k[2];

    // ---- k4 ----
    dyn9(t, u0, txI, tyI, tzI, A0, A1, A2, g0, g1, g2, k);
    #pragma unroll
    for (int j = 0; j < 9; j++) acc[j] += k[j];

    // position: p + DT*y_vel + (DT*DT/6)*sacc
    const float WP = (float)(0.01 * 0.01 / 6.0);
    float4 oa, ob, oc;
    oa.x = fmaf(WP, sax, fmaf(H1, y[0], a.x));
    oa.y = fmaf(WP, say, fmaf(H1, y[1], a.y));
    oa.z = fmaf(WP, saz, fmaf(H1, y[2], a.z));
    oa.w = fmaf(W6, acc[0], y[0]);
    ob.x = fmaf(W6, acc[1], y[1]);
    ob.y = fmaf(W6, acc[2], y[2]);
    ob.z = fmaf(W6, acc[3], y[3]);
    ob.w = fmaf(W6, acc[4], y[4]);
    oc.x = fmaf(W6, acc[5], y[5]);
    oc.y = fmaf(W6, acc[6], y[6]);
    oc.z = fmaf(W6, acc[7], y[7]);
    oc.w = fmaf(W6, acc[8], y[8]);

    // ---- coalesced store phase ----
    __syncthreads();   // all compute-phase LDS complete before overwrite
    if (act) {
        sbuf[tid]              = oa;
        sbuf[SBUF_S + tid]     = ob;
        sbuf[2 * SBUF_S + tid] = oc;
    }
    __syncthreads();

    #pragma unroll
    for (int kk = 0; kk < 3; kk++) {
        int q  = tid + 256 * kk;
        int gq = base + q;
        if (gq < limit) {
            float4 v = sbuf[(q % 3) * SBUF_S + (q / 3)];
            __stcs(&out4[gq], v);
        }
    }
}

extern "C" void kernel_launch(void* const* d_in, const int* in_sizes, int n_in,
                              void* d_out, int out_size)
{
    const float4* st = (const float4*)d_in[0];
    const float4* u  = (const float4*)d_in[1];
    const float*  I  = (const float*)d_in[2];
    const float*  g  = (const float*)d_in[3];
    float4* out = (float4*)d_out;

    int B = in_sizes[0] / 12;
    int threads = 256;
    int blocks = (B + threads - 1) / threads;
    drone_rk4_kernel<<<blocks, threads>>>(st, u, I, g, out, B);
}

// round 16
// speedup vs baseline: 1.4396x; 1.3847x over previous
#include <cuda_runtime.h>

// Approx-MUFU helpers (relative err ~2e-7; measured harmless).
__device__ __forceinline__ float frcp_fast(float x) {
    float r; asm("rcp.approx.f32 %0, %1;" : "=f"(r) : "f"(x)); return r;
}
__device__ __forceinline__ float fsqrt_fast(float x) {
    float r; asm("sqrt.approx.f32 %0, %1;" : "=f"(r) : "f"(x)); return r;
}

// Custom sincos for moderate |x|. 3-step fused Cody-Waite reduction keeps the
// reduced argument accurate to ~1e-13 absolute, so cos(x)=±sin(r) near the
// zeros of cos retains ~ulp RELATIVE accuracy — the property the chaotic
// pitch path requires. Polys: cephes float minimax.
__device__ __forceinline__ void sincos_mid(float x, float* s, float* c) {
    const float T2OPI    = 0.63661977236758134308f;       // 2/pi
    const float PIO2_HI  = 1.57079601287841796875f;
    const float PIO2_MID = 3.1391647326015867e-07f;
    const float PIO2_LO  = 5.3903025299577648e-15f;

    float j = rintf(x * T2OPI);
    int   q = (int)j;
    float r = fmaf(j, -PIO2_HI, x);
    r = fmaf(j, -PIO2_MID, r);
    r = fmaf(j, -PIO2_LO, r);

    float r2 = r * r;
    float ps = fmaf(r2, fmaf(r2, -1.9515296e-4f, 8.3321608e-3f), -1.6666655e-1f);
    float s_r = fmaf(r * r2, ps, r);
    float pc = fmaf(r2, fmaf(r2, fmaf(r2, 2.4433157e-5f, -1.3887316e-3f), 4.1666646e-2f), -0.5f);
    float c_r = fmaf(r2, pc, 1.0f);

    bool swap = (q & 1);
    float ss = swap ? c_r : s_r;
    float cc = swap ? s_r : c_r;
    if (q & 2)       ss = -ss;
    if ((q + 1) & 2) cc = -cc;
    *s = ss; *c = cc;
}

// s = [vx,vy,vz, roll,pitch,yaw, wx,wy,wz]
__device__ __forceinline__ void dyn9(
    const float* __restrict__ s,
    float u0, float txI, float tyI, float tzI,
    float A0, float A1, float A2,
    float g0, float g1, float g2,
    float* __restrict__ d)
{
    float vx = s[0], vy = s[1], vz = s[2];
    float wx = s[6], wy = s[7], wz = s[8];

    float sr, cr, sp, cp, sy, cy;
    __sincosf(s[3], &sr, &cr);
    sincos_mid(s[4], &sp, &cp);
    __sincosf(s[5], &sy, &cy);

    // R[:, :, 2] thrust column
    float spcr = sp * cr;
    float r2x = fmaf(cy, spcr, sy * sr);
    float r2y = fmaf(sy, spcr, -(cy * sr));
    float r2z = cp * cr;

    // drag
    float n2 = fmaf(vx, vx, fmaf(vy, vy, vz * vz));
    float vn = fmaxf(fsqrt_fast(n2), 1e-8f);
    float nk = -0.05f * vn;

    d[0] = fmaf(r2x, u0, fmaf(nk, vx, g0));
    d[1] = fmaf(r2y, u0, fmaf(nk, vy, g1));
    d[2] = fmaf(r2z, u0, fmaf(nk, vz, g2));

    // omega_dot via folded gyro coefficients
    d[6] = fmaf(-A0, wy * wz, txI);
    d[7] = fmaf(-A1, wz * wx, tyI);
    d[8] = fmaf(-A2, wx * wy, tzI);

    // attitude kinematics
    float cpit = (fabsf(cp) < 1e-6f) ? 1e-6f : cp;
    float icp  = frcp_fast(cpit);
    float tp   = sp * icp;
    float q    = fmaf(sr, wy, cr * wz);
    d[3] = fmaf(tp, q, wx);
    d[4] = fmaf(cr, wy, -(sr * wz));
    d[5] = q * icp;
}

// One full RK4 step for one row whose inputs are already in registers.
__device__ __forceinline__ void rk4_row(
    float4 a, float4 b, float4 c, float4 uu,
    float iI0, float iI1, float iI2,
    float A0, float A1, float A2,
    float g0, float g1, float g2,
    float4* oa, float4* ob, float4* oc)
{
    float txI = uu.y * iI0, tyI = uu.z * iI1, tzI = uu.w * iI2;
    float u0 = uu.x;

    float y[9] = { a.w, b.x, b.y,
                   b.z, b.w, c.x,
                   c.y, c.z, c.w };

    const float H2 = 0.005f;
    const float H1 = 0.01f;
    const float W6 = (float)(0.01 / 6.0);
    const float WP = (float)(0.01 * 0.01 / 6.0);

    float k[9], t[9], acc[9];

    dyn9(y, u0, txI, tyI, tzI, A0, A1, A2, g0, g1, g2, k);
    #pragma unroll
    for (int j = 0; j < 9; j++) { acc[j] = k[j]; t[j] = fmaf(H2, k[j], y[j]); }
    float sax = k[0], say = k[1], saz = k[2];

    dyn9(t, u0, txI, tyI, tzI, A0, A1, A2, g0, g1, g2, k);
    #pragma unroll
    for (int j = 0; j < 9; j++) { acc[j] = fmaf(2.0f, k[j], acc[j]); t[j] = fmaf(H2, k[j], y[j]); }
    sax += k[0]; say += k[1]; saz += k[2];

    dyn9(t, u0, txI, tyI, tzI, A0, A1, A2, g0, g1, g2, k);
    #pragma unroll
    for (int j = 0; j < 9; j++) { acc[j] = fmaf(2.0f, k[j], acc[j]); t[j] = fmaf(H1, k[j], y[j]); }
    sax += k[0]; say += k[1]; saz += k[2];

    dyn9(t, u0, txI, tyI, tzI, A0, A1, A2, g0, g1, g2, k);
    #pragma unroll
    for (int j = 0; j < 9; j++) acc[j] += k[j];

    oa->x = fmaf(WP, sax, fmaf(H1, y[0], a.x));
    oa->y = fmaf(WP, say, fmaf(H1, y[1], a.y));
    oa->z = fmaf(WP, saz, fmaf(H1, y[2], a.z));
    oa->w = fmaf(W6, acc[0], y[0]);
    ob->x = fmaf(W6, acc[1], y[1]);
    ob->y = fmaf(W6, acc[2], y[2]);
    ob->z = fmaf(W6, acc[3], y[3]);
    ob->w = fmaf(W6, acc[4], y[4]);
    oc->x = fmaf(W6, acc[5], y[5]);
    oc->y = fmaf(W6, acc[6], y[6]);
    oc->z = fmaf(W6, acc[7], y[7]);
    oc->w = fmaf(W6, acc[8], y[8]);
}

__global__ void __launch_bounds__(256, 4)
drone_rk4_kernel(const float4* __restrict__ st4,
                 const float4* __restrict__ u4,
                 const float*  __restrict__ Ip,
                 const float*  __restrict__ gp,
                 float4* __restrict__ out4,
                 int B)
{
    int tid = threadIdx.x;
    int i0  = blockIdx.x * 512 + tid;        // item 0
    int i1  = i0 + 256;                      // item 1
    if (i0 >= B) return;
    bool has1 = (i1 < B);
    int  i1c  = has1 ? i1 : i0;              // clamp loads; stores guarded

    // ---- issue ALL loads up front (MLP=8 LDG.128) ----
    float4 a0 = __ldcs(&st4[3 * i0 + 0]);
    float4 b0 = __ldcs(&st4[3 * i0 + 1]);
    float4 c0 = __ldcs(&st4[3 * i0 + 2]);
    float4 a1 = __ldcs(&st4[3 * i1c + 0]);
    float4 b1 = __ldcs(&st4[3 * i1c + 1]);
    float4 c1 = __ldcs(&st4[3 * i1c + 2]);
    float4 u0v = __ldcs(&u4[i0]);
    float4 u1v = __ldcs(&u4[i1c]);

    float I0 = __ldg(Ip + 0), I1 = __ldg(Ip + 1), I2 = __ldg(Ip + 2);
    float g0 = __ldg(gp + 0), g1 = __ldg(gp + 1), g2 = __ldg(gp + 2);
    float iI0 = __frcp_rn(I0), iI1 = __frcp_rn(I1), iI2 = __frcp_rn(I2);
    float A0 = (I2 - I1) * iI0;
    float A1 = (I0 - I2) * iI1;
    float A2 = (I1 - I0) * iI2;

    // ---- item 0 (item 1's loads complete during this body) ----
    float4 oa, ob, oc;
    rk4_row(a0, b0, c0, u0v, iI0, iI1, iI2, A0, A1, A2, g0, g1, g2, &oa, &ob, &oc);
    __stcs(&out4[3 * i0 + 0], oa);
    __stcs(&out4[3 * i0 + 1], ob);
    __stcs(&out4[3 * i0 + 2], oc);

    // ---- item 1 ----
    if (has1) {
        rk4_row(a1, b1, c1, u1v, iI0, iI1, iI2, A0, A1, A2, g0, g1, g2, &oa, &ob, &oc);
        __stcs(&out4[3 * i1 + 0], oa);
        __stcs(&out4[3 * i1 + 1], ob);
        __stcs(&out4[3 * i1 + 2], oc);
    }
}

extern "C" void kernel_launch(void* const* d_in, const int* in_sizes, int n_in,
                              void* d_out, int out_size)
{
    const float4* st = (const float4*)d_in[0];
    const float4* u  = (const float4*)d_in[1];
    const float*  I  = (const float*)d_in[2];
    const float*  g  = (const float*)d_in[3];
    float4* out = (float4*)d_out;

    int B = in_sizes[0] / 12;
    int blocks = (B + 511) / 512;            // 512 rows per block (2 per thread)
    drone_rk4_kernel<<<blocks, 256>>>(st, u, I, g, out, B);
}